// round 14
// baseline (speedup 1.0000x reference)
#include <cuda_runtime.h>
#include <cuda_bf16.h>
#include <cstdint>

// VQ-VAE eval forward, GB300 (sm_103a die, sm_103 base-ISA target).
// Round 13: 32 warps (8/SMSP), 16x32 per-warp tile. Round-12 profile: tensor
// pipe 14.4% busy, issue 22.2%, 45 cyc/HMMA/SMSP at 4 warps vs 51 at 2 ->
// fallback mma.sync looks PER-WARP serialized (~1 in flight/warp). Throughput
// ~ n_warps/latency, so max out warps: 1024 threads, 64-reg cap, full RF.
// Numerics identical to rounds 6-12 (bf16 HMMA shortlist -> top-8 band ->
// exact fp32 reference re-rank; rel_err 4.23e-7 across all).

#define KC      2048
#define DD      256
#define BETA_F  0.25f
#define MAXROWS 32768
#define MARGIN  0.05f

#define TILE_M  128
#define TILE_N  128
#define NTILES  (KC / TILE_N)     // 16
#define NTHREADS 1024

// smem layout (bytes)
#define APITCH  264               // bf16 units per A row (256 + 8 pad)
#define BPITCH  136               // bf16 units per B row (128 + 8 pad); 17 uint4
#define OFF_A   0
#define ABYTES  (TILE_M * APITCH * 2)              // 67584
#define OFF_B   ABYTES
#define BBYTES  (TILE_N * BPITCH * 2)              // 34816
#define OFF_US  (OFF_B + 2 * BBYTES)               // 137216
#define USBYTES (128 * 128 * 4)                    // 65536
#define OFF_E2  (OFF_US + USBYTES)                 // 202752
#define SMEM_TOTAL (OFF_E2 + 512)                  // 203264

// ---- static device scratch ----
__device__ float          g_e2[KC];
__device__ __nv_bfloat16  g_Wbf[KC * DD];
__device__ int            g_cand[MAXROWS * 8];
__device__ int            g_ncand[MAXROWS];
__device__ int            g_counts[KC];
__device__ float          g_partials[MAXROWS];

// ============================================================================
// helpers
// ============================================================================
__device__ __forceinline__ uint32_t smem_u32(const void* p) {
    uint32_t a;
    asm("{ .reg .u64 t; cvta.to.shared.u64 t, %1; cvt.u32.u64 %0, t; }" : "=r"(a) : "l"(p));
    return a;
}
__device__ __forceinline__ void ldsm_x4(uint32_t& r0, uint32_t& r1, uint32_t& r2,
                                        uint32_t& r3, uint32_t addr) {
    asm volatile("ldmatrix.sync.aligned.m8n8.x4.shared.b16 {%0,%1,%2,%3}, [%4];"
                 : "=r"(r0), "=r"(r1), "=r"(r2), "=r"(r3) : "r"(addr));
}
__device__ __forceinline__ void mma16816(float* c, const uint32_t* a, const uint32_t* b) {
    asm volatile("mma.sync.aligned.m16n8k16.row.col.f32.bf16.bf16.f32 "
                 "{%0,%1,%2,%3}, {%4,%5,%6,%7}, {%8,%9}, {%0,%1,%2,%3};"
                 : "+f"(c[0]), "+f"(c[1]), "+f"(c[2]), "+f"(c[3])
                 : "r"(a[0]), "r"(a[1]), "r"(a[2]), "r"(a[3]), "r"(b[0]), "r"(b[1]));
}
__device__ __forceinline__ int fswz(int r) {
    return (r & 1) | (((r >> 3) & 3) << 1) | (((r >> 1) & 3) << 3);
}

// ============================================================================
// prep kernels (launch order keeps the HMMA kernel at profiled index 3)
// ============================================================================
__global__ void vq_prep_e2_kernel(const float* __restrict__ W) {
    int row = blockIdx.x, tid = threadIdx.x;
    float w = W[(size_t)row * DD + tid];
    __shared__ float red[256];
    red[tid] = w * w;
    __syncthreads();
    for (int s = 128; s > 0; s >>= 1) {
        if (tid < s) red[tid] += red[tid + s];
        __syncthreads();
    }
    if (tid == 0) { g_e2[row] = red[0]; g_counts[row] = 0; }
}

__global__ void vq_prep_wbf_kernel(const float* __restrict__ W) {
    int i = blockIdx.x * 256 + threadIdx.x;
    g_Wbf[i] = __float2bfloat16_rn(W[i]);
}

__global__ void vq_zero_ncand_kernel(int n_rows) {
    int i = blockIdx.x * 256 + threadIdx.x;
    if (i < n_rows) g_ncand[i] = 0;
}

// ============================================================================
// phase 1: HMMA approx-score GEMM + per-row top-8 candidate band.
// 1024 threads, 32 warps: 8 (wm, 16 rows) x 4 (wn, 32 cols). grid = n_rows/128.
// ============================================================================
__global__ __launch_bounds__(NTHREADS, 1)
void vq_hmma_kernel(const float* __restrict__ Z) {
    extern __shared__ char smem[];
    const uint32_t sb = smem_u32(smem);
    const int tid = threadIdx.x;
    const int lane = tid & 31, wid = tid >> 5;
    const int wm = wid & 7, wn = wid >> 3;     // wm: 16-row group, wn: 32-col group
    const int grp = lane >> 3, lr = lane & 7;
    const int rowBase = blockIdx.x * TILE_M;
    float* Us = (float*)(smem + OFF_US);
    float* e2s = (float*)(smem + OFF_E2);

    // ---- ldmatrix lane addresses ----
    const uint32_t aAddr = sb + OFF_A +
        (uint32_t)((wm * 16 + (grp & 1) * 8 + lr) * APITCH + (grp >> 1) * 8) * 2u;
    uint32_t bAddr[2];
#pragma unroll
    for (int p = 0; p < 2; ++p) {
        int n = wn * 32 + p * 16 + (grp >> 1) * 8 + lr;
        int kof = (grp & 1) * 8;
        bAddr[p] = sb + OFF_B + (uint32_t)(n * BPITCH + kof) * 2u;
    }

    // ---- load A tile: 128 rows x 256 dims fp32 -> bf16 smem (8 thr/row) ----
    {
        int r = tid >> 3, q = tid & 7;
        const float4* src = (const float4*)(Z + (size_t)(rowBase + r) * DD + q * 32);
        __nv_bfloat162* dst = (__nv_bfloat162*)(smem + OFF_A) + r * (APITCH / 2) + q * 16;
#pragma unroll
        for (int j = 0; j < 8; ++j) {
            float4 v = src[j];
            dst[j * 2]     = __float22bfloat162_rn(make_float2(v.x, v.y));
            dst[j * 2 + 1] = __float22bfloat162_rn(make_float2(v.z, v.w));
        }
    }

    // ---- top-8 state (ascending u; u0 = min) ----
    float u0 = 3.4e38f, u1 = 3.4e38f, u2 = 3.4e38f, u3 = 3.4e38f,
          u4 = 3.4e38f, u5 = 3.4e38f, u6 = 3.4e38f, u7 = 3.4e38f;
    int   k0 = 0, k1 = 0, k2 = 0, k3 = 0, k4 = 0, k5 = 0, k6 = 0, k7 = 0;
    const int myf = fswz(tid & 127);

    float acc[4][4];
    uint4 rb[2];

    // prefetch B tile 0 (32KB: 8 thr/code-row, 32B each)
    {
        int n = tid >> 3, q = tid & 7;
        const uint4* src = (const uint4*)g_Wbf + (size_t)n * 32 + q * 2;
        rb[0] = src[0]; rb[1] = src[1];
    }

    for (int t = 0; t < 2 * NTILES; ++t) {
        const int nt = t >> 1, kt = t & 1, buf = t & 1;
        const uint32_t bufOff = (uint32_t)buf * BBYTES;

        __syncthreads();                       // prior readers of Bs[buf] done
        {   // store prefetched regs -> Bs[buf]
            int n = tid >> 3, q = tid & 7;
            uint4* dst = (uint4*)(smem + OFF_B + bufOff) + n * (BPITCH / 8) + q * 2;
            dst[0] = rb[0]; dst[1] = rb[1];
        }
        if (kt == 0 && tid < 128) e2s[tid] = g_e2[nt * 128 + tid];
        if (t + 1 < 2 * NTILES) {              // prefetch next tile
            int tn = t + 1;
            int n = tid >> 3, q = tid & 7;
            const uint4* src = (const uint4*)g_Wbf
                + (size_t)((tn >> 1) * 128 + n) * 32 + (tn & 1) * 16 + q * 2;
            rb[0] = src[0]; rb[1] = src[1];
        }
        __syncthreads();                       // Bs[buf] visible

        if (kt == 0) {
#pragma unroll
            for (int nf = 0; nf < 4; ++nf)
#pragma unroll
                for (int c = 0; c < 4; ++c) acc[nf][c] = 0.0f;
        }

#pragma unroll
        for (int ks = 0; ks < 8; ++ks) {
            uint32_t a[4], b[4][2];
            ldsm_x4(a[0], a[1], a[2], a[3],
                    aAddr + (uint32_t)(kt * 128 + ks * 16) * 2u);
#pragma unroll
            for (int p = 0; p < 2; ++p)
                ldsm_x4(b[2 * p][0], b[2 * p][1], b[2 * p + 1][0], b[2 * p + 1][1],
                        bAddr[p] + bufOff + (uint32_t)(ks * 16) * 2u);
#pragma unroll
            for (int nf = 0; nf < 4; ++nf)
                mma16816(acc[nf], a, b[nf]);
        }

        if (kt == 1) {
            // ---- stage u = e2 - 2*d into swizzled smem ----
            int r0 = wm * 16 + (lane >> 2);
            int r1 = r0 + 8;
#pragma unroll
            for (int nf = 0; nf < 4; ++nf) {
                int c0 = wn * 32 + nf * 8 + 2 * (lane & 3);
                float e0 = e2s[c0], e1 = e2s[c0 + 1];
                Us[r0 * 128 + ((c0)     ^ fswz(r0))] = fmaf(-2.0f, acc[nf][0], e0);
                Us[r0 * 128 + ((c0 + 1) ^ fswz(r0))] = fmaf(-2.0f, acc[nf][1], e1);
                Us[r1 * 128 + ((c0)     ^ fswz(r1))] = fmaf(-2.0f, acc[nf][2], e0);
                Us[r1 * 128 + ((c0 + 1) ^ fswz(r1))] = fmaf(-2.0f, acc[nf][3], e1);
            }
            __syncthreads();
            if (tid < 128) {
                const float* urow = Us + tid * 128;
                int kbase = nt * 128;
#pragma unroll 4
                for (int c = 0; c < 128; ++c) {
                    float u = urow[c ^ myf];
                    if (u < u7) {
                        u7 = u; k7 = kbase + c;
                        if (u7 < u6) { float tu = u6; u6 = u7; u7 = tu; int tk = k6; k6 = k7; k7 = tk; }
                        if (u6 < u5) { float tu = u5; u5 = u6; u6 = tu; int tk = k5; k5 = k6; k6 = tk; }
                        if (u5 < u4) { float tu = u4; u4 = u5; u5 = tu; int tk = k4; k4 = k5; k5 = tk; }
                        if (u4 < u3) { float tu = u3; u3 = u4; u4 = tu; int tk = k3; k3 = k4; k4 = tk; }
                        if (u3 < u2) { float tu = u2; u2 = u3; u3 = tu; int tk = k2; k2 = k3; k3 = tk; }
                        if (u2 < u1) { float tu = u1; u1 = u2; u2 = tu; int tk = k1; k1 = k2; k2 = tk; }
                        if (u1 < u0) { float tu = u0; u0 = u1; u1 = tu; int tk = k0; k0 = k1; k1 = tk; }
                    }
                }
            }
            // scan finishes before the next loop-top __syncthreads
        }
    }

    if (tid < 128) {
        int row = rowBase + tid;
        float thr = u0 + MARGIN;
        int cnt = 1 + (u1 <= thr) + (u2 <= thr) + (u3 <= thr) + (u4 <= thr)
                    + (u5 <= thr) + (u6 <= thr) + (u7 <= thr);
        g_cand[row * 8 + 0] = k0; g_cand[row * 8 + 1] = k1;
        g_cand[row * 8 + 2] = k2; g_cand[row * 8 + 3] = k3;
        g_cand[row * 8 + 4] = k4; g_cand[row * 8 + 5] = k5;
        g_cand[row * 8 + 6] = k6; g_cand[row * 8 + 7] = k7;
        g_ncand[row] = (cnt == 8) ? 9 : cnt;   // 9 = overflow -> exact full scan
    }
}

// ============================================================================
// phase 2: exact fp32 re-rank of candidates (reference ranking pipeline,
// lexicographic (s,k) == first-index ties) fused with gather/MSE/histogram.
// warp per row; grid = n_rows/8, block 256.
// ============================================================================
__global__ __launch_bounds__(256)
void vq_refine_gather_kernel(const float* __restrict__ Z, const float* __restrict__ W,
                             float* __restrict__ out, int n_rows, int write_idx) {
    const int lane = threadIdx.x & 31;
    const int row = blockIdx.x * 8 + (threadIdx.x >> 5);

    float4 z0 = *(const float4*)&Z[(size_t)row * DD + lane * 8];
    float4 z1 = *(const float4*)&Z[(size_t)row * DD + lane * 8 + 4];
    float p = z0.x * z0.x + z0.y * z0.y + z0.z * z0.z + z0.w * z0.w
            + z1.x * z1.x + z1.y * z1.y + z1.z * z1.z + z1.w * z1.w;
#pragma unroll
    for (int off = 16; off > 0; off >>= 1) p += __shfl_xor_sync(0xffffffffu, p, off);
    const float z2 = p;

    int nc = g_ncand[row];
    float sbest = 3.4e38f;
    int kbest = 0;
    int iters = (nc <= 8) ? nc : KC;
    for (int i = 0; i < iters; ++i) {
        int k = (nc <= 8) ? g_cand[row * 8 + i] : i;
        float4 w0 = *(const float4*)&W[(size_t)k * DD + lane * 8];
        float4 w1 = *(const float4*)&W[(size_t)k * DD + lane * 8 + 4];
        float d = z0.x * w0.x + z0.y * w0.y + z0.z * w0.z + z0.w * w0.w
                + z1.x * w1.x + z1.y * w1.y + z1.z * w1.z + z1.w * w1.w;
#pragma unroll
        for (int off = 16; off > 0; off >>= 1) d += __shfl_xor_sync(0xffffffffu, d, off);
        float u = (z2 - 2.0f * d) + g_e2[k];
        float s = sqrtf(fmaxf(u, 0.0f));
        if (s < sbest || (s == sbest && k < kbest)) { sbest = s; kbest = k; }
    }

    // ---- gather + MSE partial + histogram ----
    float4 w0 = *(const float4*)&W[(size_t)kbest * DD + lane * 8];
    float4 w1 = *(const float4*)&W[(size_t)kbest * DD + lane * 8 + 4];
    float d0 = w0.x - z0.x, d1 = w0.y - z0.y, d2 = w0.z - z0.z, d3 = w0.w - z0.w;
    float d4 = w1.x - z1.x, d5 = w1.y - z1.y, d6 = w1.z - z1.z, d7 = w1.w - z1.w;
    *(float4*)&out[(size_t)row * DD + lane * 8] =
        make_float4(z0.x + d0, z0.y + d1, z0.z + d2, z0.w + d3);
    *(float4*)&out[(size_t)row * DD + lane * 8 + 4] =
        make_float4(z1.x + d4, z1.y + d5, z1.z + d6, z1.w + d7);
    float sq = d0 * d0 + d1 * d1 + d2 * d2 + d3 * d3
             + d4 * d4 + d5 * d5 + d6 * d6 + d7 * d7;
#pragma unroll
    for (int off = 16; off > 0; off >>= 1) sq += __shfl_xor_sync(0xffffffffu, sq, off);
    if (lane == 0) {
        g_partials[row] = sq;
        atomicAdd(&g_counts[kbest], 1);
        if (write_idx) out[(size_t)n_rows * DD + 1 + row] = (float)kbest;
    }
}

// ============================================================================
// loss: deterministic reductions; vq_loss = (1+beta)*MSE - 0.01*perplexity
// ============================================================================
__global__ void vq_loss_kernel(float* __restrict__ out, int n_rows, int write_loss) {
    int tid = threadIdx.x;
    float s = 0.0f;
    for (int i = tid; i < n_rows; i += 1024) s += g_partials[i];
    float h = 0.0f;
    for (int k = tid; k < KC; k += 1024) {
        float p = (float)g_counts[k] / (float)n_rows;
        h -= p * logf(p + 1e-10f);
    }
    __shared__ float rs[1024];
    __shared__ float rh[1024];
    rs[tid] = s; rh[tid] = h;
    __syncthreads();
    for (int st = 512; st > 0; st >>= 1) {
        if (tid < st) { rs[tid] += rs[tid + st]; rh[tid] += rh[tid + st]; }
        __syncthreads();
    }
    if (tid == 0 && write_loss) {
        float mse = rs[0] / ((float)n_rows * (float)DD);
        float perplexity = expf(rh[0]);
        out[(size_t)n_rows * DD] = (1.0f + BETA_F) * mse - 0.01f * perplexity;
    }
}

// ============================================================================
extern "C" void kernel_launch(void* const* d_in, const int* in_sizes, int n_in,
                              void* d_out, int out_size) {
    (void)n_in;
    const float* Z = (const float*)d_in[0];   // z_e  [8,4096,256] fp32
    const float* W = (const float*)d_in[1];   // embed [2048,256] fp32
    float* out = (float*)d_out;

    int D = in_sizes[1] / KC;                  // 256
    int n_rows = in_sizes[0] / D;              // 32768
    long long nzq = (long long)n_rows * D;
    int write_loss = (out_size >= nzq + 1) ? 1 : 0;
    int write_idx  = (out_size >= nzq + 1 + n_rows) ? 1 : 0;

    cudaFuncSetAttribute(vq_hmma_kernel,
                         cudaFuncAttributeMaxDynamicSharedMemorySize, SMEM_TOTAL);

    vq_prep_e2_kernel<<<KC, 256>>>(W);                           // idx 0
    vq_prep_wbf_kernel<<<(KC * DD) / 256, 256>>>(W);             // idx 1
    vq_zero_ncand_kernel<<<(n_rows + 255) / 256, 256>>>(n_rows); // idx 2
    vq_hmma_kernel<<<n_rows / TILE_M, NTHREADS, SMEM_TOTAL>>>(Z); // idx 3 (profiled)
    vq_refine_gather_kernel<<<n_rows / 8, 256>>>(Z, W, out, n_rows, write_idx);
    vq_loss_kernel<<<1, 1024>>>(out, n_rows, write_loss);
}

// round 15
// speedup vs baseline: 1.0882x; 1.0882x over previous
#include <cuda_runtime.h>
#include <cuda_bf16.h>
#include <cstdint>

// VQ-VAE eval forward, GB300 (sm_103a die, sm_103 base-ISA target).
// Round 14: wave-balance fix. r12/r13 established a hard wall ~45cyc per
// mma.sync.16816 per SMSP (warp count 2/4/8 per SMSP -> 51/45/49 cyc: flat).
// r12's 390us = 637k cyc of wall work / 0.86 wave efficiency (256 CTAs/148
// SMs = 1.73 waves). Fix: TILE_M=32, grid=1024 (6.92 units/SM, ~1% tail),
// 2 CTAs/SM, cp.async-fed B double buffer, stripe-parallel top-8 scan with
// end merge. Shortlist numerics unchanged (bf16 HMMA -> top-8 band ->
// exact fp32 reference re-rank; rel_err 4.23e-7 in all passing rounds).

#define KC      2048
#define DD      256
#define BETA_F  0.25f
#define MAXROWS 32768
#define MARGIN  0.05f

#define TILE_M  32
#define TILE_N  128
#define NTILES  (KC / TILE_N)     // 16
#define NCHUNK  (2 * NTILES)      // 32 (nt x kt)
#define NTHREADS 512

// smem layout (bytes)
#define APITCH  264               // bf16 units per A row (256 + 8 pad)
#define BPITCH  136               // bf16 units per B code row (128 + 8 pad)
#define OFF_A   0
#define ABYTES  (TILE_M * APITCH * 2)              // 16896
#define OFF_B   ABYTES
#define BBYTES  (TILE_N * BPITCH * 2)              // 34816
#define OFF_US  (OFF_B + 2 * BBYTES)               // 86528
#define USBYTES (TILE_M * 128 * 4)                 // 16384
#define OFF_E2  (OFF_US + USBYTES)                 // 102912
#define SMEM_TOTAL (OFF_E2 + KC * 4)               // 111104 (2 CTAs/SM)

// ---- static device scratch ----
__device__ float          g_e2[KC];
__device__ __nv_bfloat16  g_Wbf[KC * DD];
__device__ int            g_cand[MAXROWS * 8];
__device__ int            g_ncand[MAXROWS];
__device__ int            g_counts[KC];
__device__ float          g_partials[MAXROWS];

// ============================================================================
// helpers
// ============================================================================
__device__ __forceinline__ uint32_t smem_u32(const void* p) {
    uint32_t a;
    asm("{ .reg .u64 t; cvta.to.shared.u64 t, %1; cvt.u32.u64 %0, t; }" : "=r"(a) : "l"(p));
    return a;
}
__device__ __forceinline__ void ldsm_x4(uint32_t& r0, uint32_t& r1, uint32_t& r2,
                                        uint32_t& r3, uint32_t addr) {
    asm volatile("ldmatrix.sync.aligned.m8n8.x4.shared.b16 {%0,%1,%2,%3}, [%4];"
                 : "=r"(r0), "=r"(r1), "=r"(r2), "=r"(r3) : "r"(addr));
}
__device__ __forceinline__ void mma16816(float* c, const uint32_t* a, const uint32_t* b) {
    asm volatile("mma.sync.aligned.m16n8k16.row.col.f32.bf16.bf16.f32 "
                 "{%0,%1,%2,%3}, {%4,%5,%6,%7}, {%8,%9}, {%0,%1,%2,%3};"
                 : "+f"(c[0]), "+f"(c[1]), "+f"(c[2]), "+f"(c[3])
                 : "r"(a[0]), "r"(a[1]), "r"(a[2]), "r"(a[3]), "r"(b[0]), "r"(b[1]));
}
__device__ __forceinline__ void cp_async16(uint32_t dst, const void* src) {
    asm volatile("cp.async.cg.shared.global [%0], [%1], 16;" :: "r"(dst), "l"(src));
}
#define CP_COMMIT() asm volatile("cp.async.commit_group;" ::: "memory")
#define CP_WAIT1()  asm volatile("cp.async.wait_group 1;" ::: "memory")

__device__ __forceinline__ int fswz(int r) {
    return (r & 1) | (((r >> 3) & 3) << 1) | (((r >> 1) & 3) << 3);
}

// ============================================================================
// prep kernels (launch order keeps the HMMA kernel at profiled index 3)
// ============================================================================
__global__ void vq_prep_e2_kernel(const float* __restrict__ W) {
    int row = blockIdx.x, tid = threadIdx.x;
    float w = W[(size_t)row * DD + tid];
    __shared__ float red[256];
    red[tid] = w * w;
    __syncthreads();
    for (int s = 128; s > 0; s >>= 1) {
        if (tid < s) red[tid] += red[tid + s];
        __syncthreads();
    }
    if (tid == 0) { g_e2[row] = red[0]; g_counts[row] = 0; }
}

__global__ void vq_prep_wbf_kernel(const float* __restrict__ W) {
    int i = blockIdx.x * 256 + threadIdx.x;
    g_Wbf[i] = __float2bfloat16_rn(W[i]);
}

__global__ void vq_zero_ncand_kernel(int n_rows) {
    int i = blockIdx.x * 256 + threadIdx.x;
    if (i < n_rows) g_ncand[i] = 0;
}

// ============================================================================
// phase 1: HMMA approx-score GEMM + per-row top-8 candidate band.
// 512 threads, 16 warps: wm in {0,1} (16 rows), wn in 0..7 (16 cols each).
// grid = n_rows/32 = 1024 units -> ~1% wave-quantization loss at 148 SMs.
// ============================================================================
__global__ __launch_bounds__(NTHREADS, 2)
void vq_hmma_kernel(const float* __restrict__ Z) {
    extern __shared__ char smem[];
    const uint32_t sb = smem_u32(smem);
    const int tid = threadIdx.x;
    const int lane = tid & 31, wid = tid >> 5;
    const int wm = wid & 1, wn = wid >> 1;
    const int grp = lane >> 3, lr = lane & 7;
    const int rowBase = blockIdx.x * TILE_M;
    float* Us  = (float*)(smem + OFF_US);
    float* e2s = (float*)(smem + OFF_E2);

    // ---- ldmatrix lane addresses ----
    const uint32_t aAddr = sb + OFF_A +
        (uint32_t)((wm * 16 + (grp & 1) * 8 + lr) * APITCH + (grp >> 1) * 8) * 2u;
    const uint32_t bAddr = sb + OFF_B +
        (uint32_t)((wn * 16 + (grp >> 1) * 8 + lr) * BPITCH + (grp & 1) * 8) * 2u;

    // ---- load A tile (32 rows x 256 fp32 -> bf16) + full e2 (2048 floats) ----
    {
#pragma unroll
        for (int j = 0; j < 4; ++j) {
            int o = tid + 512 * j;            // 0..2047 float4s
            int r = o >> 6, c = o & 63;
            float4 v = *(const float4*)&Z[(size_t)(rowBase + r) * DD + c * 4];
            __nv_bfloat162* dst = (__nv_bfloat162*)(smem + OFF_A) + r * (APITCH / 2) + c * 2;
            dst[0] = __float22bfloat162_rn(make_float2(v.x, v.y));
            dst[1] = __float22bfloat162_rn(make_float2(v.z, v.w));
        }
#pragma unroll
        for (int j = 0; j < 4; ++j) {
            int i = tid + 512 * j;
            e2s[i] = g_e2[i];
        }
    }

    // ---- prologue: issue B chunks 0 and 1 (cp.async, one group each) ----
#pragma unroll
    for (int g = 0; g < 2; ++g) {
        int nt = g >> 1, kt = g & 1, buf = g & 1;
#pragma unroll
        for (int j = 0; j < 4; ++j) {
            int o = tid + 512 * j;            // 0..2047 16B ops
            int n = o >> 4, seg = o & 15;
            const void* src = g_Wbf + (size_t)(nt * 128 + n) * DD + kt * 128 + seg * 8;
            cp_async16(sb + OFF_B + (uint32_t)buf * BBYTES
                       + (uint32_t)(n * BPITCH + seg * 8) * 2u, src);
        }
        CP_COMMIT();
    }

    // ---- per-thread top-8 (scan threads tid<128: row = tid>>2, stripe = tid&3)
    float u0 = 3.4e38f, u1 = 3.4e38f, u2 = 3.4e38f, u3 = 3.4e38f,
          u4 = 3.4e38f, u5 = 3.4e38f, u6 = 3.4e38f, u7 = 3.4e38f;
    int   k0 = 0, k1 = 0, k2 = 0, k3 = 0, k4 = 0, k5 = 0, k6 = 0, k7 = 0;
    const int srow = tid >> 2, sstripe = tid & 3;
    const int myf = fswz(srow & 31);

    float acc[2][4];

    for (int g = 0; g < NCHUNK; ++g) {
        const int nt = g >> 1, kt = g & 1, buf = g & 1;
        const uint32_t bufOff = (uint32_t)buf * BBYTES;

        CP_WAIT1();                 // chunk g landed
        __syncthreads();

        if (kt == 0) {
#pragma unroll
            for (int nf = 0; nf < 2; ++nf)
#pragma unroll
                for (int c = 0; c < 4; ++c) acc[nf][c] = 0.0f;
        }

#pragma unroll
        for (int ks = 0; ks < 8; ++ks) {
            uint32_t a[4], b[4];
            ldsm_x4(a[0], a[1], a[2], a[3],
                    aAddr + (uint32_t)(kt * 128 + ks * 16) * 2u);
            ldsm_x4(b[0], b[1], b[2], b[3],
                    bAddr + bufOff + (uint32_t)(ks * 16) * 2u);
            mma16816(acc[0], a, &b[0]);       // cols wn*16 + 0..7
            mma16816(acc[1], a, &b[2]);       // cols wn*16 + 8..15
        }

        if (kt == 1) {
            // ---- stage u = e2 - 2*d into swizzled Us ----
            int r0 = wm * 16 + (lane >> 2);
            int r1 = r0 + 8;
#pragma unroll
            for (int nf = 0; nf < 2; ++nf) {
                int c0 = wn * 16 + nf * 8 + 2 * (lane & 3);
                float e0 = e2s[nt * 128 + c0], e1 = e2s[nt * 128 + c0 + 1];
                Us[r0 * 128 + ((c0)     ^ fswz(r0))] = fmaf(-2.0f, acc[nf][0], e0);
                Us[r0 * 128 + ((c0 + 1) ^ fswz(r0))] = fmaf(-2.0f, acc[nf][1], e1);
                Us[r1 * 128 + ((c0)     ^ fswz(r1))] = fmaf(-2.0f, acc[nf][2], e0);
                Us[r1 * 128 + ((c0 + 1) ^ fswz(r1))] = fmaf(-2.0f, acc[nf][3], e1);
            }
            __syncthreads();
            if (tid < 128) {
                const float* urow = Us + srow * 128;
                int kbase = nt * 128 + sstripe * 32;
#pragma unroll 4
                for (int j = 0; j < 32; ++j) {
                    int c = sstripe * 32 + j;
                    float u = urow[c ^ myf];
                    if (u < u7) {
                        u7 = u; k7 = kbase + j;
                        if (u7 < u6) { float tu = u6; u6 = u7; u7 = tu; int tk = k6; k6 = k7; k7 = tk; }
                        if (u6 < u5) { float tu = u5; u5 = u6; u6 = tu; int tk = k5; k5 = k6; k6 = tk; }
                        if (u5 < u4) { float tu = u4; u4 = u5; u5 = tu; int tk = k4; k4 = k5; k5 = tk; }
                        if (u4 < u3) { float tu = u3; u3 = u4; u4 = tu; int tk = k3; k3 = k4; k4 = tk; }
                        if (u3 < u2) { float tu = u2; u2 = u3; u3 = tu; int tk = k2; k2 = k3; k3 = tk; }
                        if (u2 < u1) { float tu = u1; u1 = u2; u2 = tu; int tk = k1; k1 = k2; k2 = tk; }
                        if (u1 < u0) { float tu = u0; u0 = u1; u1 = tu; int tk = k0; k0 = k1; k1 = tk; }
                    }
                }
            }
        }

        __syncthreads();            // buf free for refill; Us scan complete
        if (g + 2 < NCHUNK) {       // issue chunk g+2 into this buf
            int gn = g + 2;
            int nnt = gn >> 1, nkt = gn & 1;
#pragma unroll
            for (int j = 0; j < 4; ++j) {
                int o = tid + 512 * j;
                int n = o >> 4, seg = o & 15;
                const void* src = g_Wbf + (size_t)(nnt * 128 + n) * DD + nkt * 128 + seg * 8;
                cp_async16(sb + OFF_B + bufOff + (uint32_t)(n * BPITCH + seg * 8) * 2u, src);
            }
        }
        CP_COMMIT();                // commit (possibly empty) group: keeps wait bookkeeping uniform
    }

    // ---- merge 4 stripes per row, then band + write ----
    float* us_m = (float*)(smem + OFF_US);
    int*   ks_m = (int*)(smem + OFF_US + 4096);
    if (tid < 128) {
        us_m[tid * 8 + 0] = u0; ks_m[tid * 8 + 0] = k0;
        us_m[tid * 8 + 1] = u1; ks_m[tid * 8 + 1] = k1;
        us_m[tid * 8 + 2] = u2; ks_m[tid * 8 + 2] = k2;
        us_m[tid * 8 + 3] = u3; ks_m[tid * 8 + 3] = k3;
        us_m[tid * 8 + 4] = u4; ks_m[tid * 8 + 4] = k4;
        us_m[tid * 8 + 5] = u5; ks_m[tid * 8 + 5] = k5;
        us_m[tid * 8 + 6] = u6; ks_m[tid * 8 + 6] = k6;
        us_m[tid * 8 + 7] = u7; ks_m[tid * 8 + 7] = k7;
    }
    __syncthreads();
    if (tid < TILE_M) {
        float m0 = 3.4e38f, m1 = 3.4e38f, m2 = 3.4e38f, m3 = 3.4e38f,
              m4 = 3.4e38f, m5 = 3.4e38f, m6 = 3.4e38f, m7 = 3.4e38f;
        int   c0 = 0, c1 = 0, c2 = 0, c3 = 0, c4 = 0, c5 = 0, c6 = 0, c7 = 0;
        for (int e = 0; e < 32; ++e) {
            float u = us_m[(tid * 4) * 8 + e];      // 4 stripes x 8, contiguous
            int   k = ks_m[(tid * 4) * 8 + e];
            if (u < m7) {
                m7 = u; c7 = k;
                if (m7 < m6) { float tu = m6; m6 = m7; m7 = tu; int tk = c6; c6 = c7; c7 = tk; }
                if (m6 < m5) { float tu = m5; m5 = m6; m6 = tu; int tk = c5; c5 = c6; c6 = tk; }
                if (m5 < m4) { float tu = m4; m4 = m5; m5 = tu; int tk = c4; c4 = c5; c5 = tk; }
                if (m4 < m3) { float tu = m3; m3 = m4; m4 = tu; int tk = c3; c3 = c4; c4 = tk; }
                if (m3 < m2) { float tu = m2; m2 = m3; m3 = tu; int tk = c2; c2 = c3; c3 = tk; }
                if (m2 < m1) { float tu = m1; m1 = m2; m2 = tu; int tk = c1; c1 = c2; c2 = tk; }
                if (m1 < m0) { float tu = m0; m0 = m1; m1 = tu; int tk = c0; c0 = c1; c1 = tk; }
            }
        }
        int row = rowBase + tid;
        float thr = m0 + MARGIN;
        int cnt = 1 + (m1 <= thr) + (m2 <= thr) + (m3 <= thr) + (m4 <= thr)
                    + (m5 <= thr) + (m6 <= thr) + (m7 <= thr);
        g_cand[row * 8 + 0] = c0; g_cand[row * 8 + 1] = c1;
        g_cand[row * 8 + 2] = c2; g_cand[row * 8 + 3] = c3;
        g_cand[row * 8 + 4] = c4; g_cand[row * 8 + 5] = c5;
        g_cand[row * 8 + 6] = c6; g_cand[row * 8 + 7] = c7;
        g_ncand[row] = (cnt == 8) ? 9 : cnt;   // 9 = overflow -> exact full scan
    }
}

// ============================================================================
// phase 2: exact fp32 re-rank of candidates (reference ranking pipeline,
// lexicographic (s,k) == first-index ties) fused with gather/MSE/histogram.
// warp per row; grid = n_rows/8, block 256.
// ============================================================================
__global__ __launch_bounds__(256)
void vq_refine_gather_kernel(const float* __restrict__ Z, const float* __restrict__ W,
                             float* __restrict__ out, int n_rows, int write_idx) {
    const int lane = threadIdx.x & 31;
    const int row = blockIdx.x * 8 + (threadIdx.x >> 5);

    float4 z0 = *(const float4*)&Z[(size_t)row * DD + lane * 8];
    float4 z1 = *(const float4*)&Z[(size_t)row * DD + lane * 8 + 4];
    float p = z0.x * z0.x + z0.y * z0.y + z0.z * z0.z + z0.w * z0.w
            + z1.x * z1.x + z1.y * z1.y + z1.z * z1.z + z1.w * z1.w;
#pragma unroll
    for (int off = 16; off > 0; off >>= 1) p += __shfl_xor_sync(0xffffffffu, p, off);
    const float z2 = p;

    int nc = g_ncand[row];
    float sbest = 3.4e38f;
    int kbest = 0;
    int iters = (nc <= 8) ? nc : KC;
    for (int i = 0; i < iters; ++i) {
        int k = (nc <= 8) ? g_cand[row * 8 + i] : i;
        float4 w0 = *(const float4*)&W[(size_t)k * DD + lane * 8];
        float4 w1 = *(const float4*)&W[(size_t)k * DD + lane * 8 + 4];
        float d = z0.x * w0.x + z0.y * w0.y + z0.z * w0.z + z0.w * w0.w
                + z1.x * w1.x + z1.y * w1.y + z1.z * w1.z + z1.w * w1.w;
#pragma unroll
        for (int off = 16; off > 0; off >>= 1) d += __shfl_xor_sync(0xffffffffu, d, off);
        float u = (z2 - 2.0f * d) + g_e2[k];
        float s = sqrtf(fmaxf(u, 0.0f));
        if (s < sbest || (s == sbest && k < kbest)) { sbest = s; kbest = k; }
    }

    // ---- gather + MSE partial + histogram ----
    float4 w0 = *(const float4*)&W[(size_t)kbest * DD + lane * 8];
    float4 w1 = *(const float4*)&W[(size_t)kbest * DD + lane * 8 + 4];
    float d0 = w0.x - z0.x, d1 = w0.y - z0.y, d2 = w0.z - z0.z, d3 = w0.w - z0.w;
    float d4 = w1.x - z1.x, d5 = w1.y - z1.y, d6 = w1.z - z1.z, d7 = w1.w - z1.w;
    *(float4*)&out[(size_t)row * DD + lane * 8] =
        make_float4(z0.x + d0, z0.y + d1, z0.z + d2, z0.w + d3);
    *(float4*)&out[(size_t)row * DD + lane * 8 + 4] =
        make_float4(z1.x + d4, z1.y + d5, z1.z + d6, z1.w + d7);
    float sq = d0 * d0 + d1 * d1 + d2 * d2 + d3 * d3
             + d4 * d4 + d5 * d5 + d6 * d6 + d7 * d7;
#pragma unroll
    for (int off = 16; off > 0; off >>= 1) sq += __shfl_xor_sync(0xffffffffu, sq, off);
    if (lane == 0) {
        g_partials[row] = sq;
        atomicAdd(&g_counts[kbest], 1);
        if (write_idx) out[(size_t)n_rows * DD + 1 + row] = (float)kbest;
    }
}

// ============================================================================
// loss: deterministic reductions; vq_loss = (1+beta)*MSE - 0.01*perplexity
// ============================================================================
__global__ void vq_loss_kernel(float* __restrict__ out, int n_rows, int write_loss) {
    int tid = threadIdx.x;
    float s = 0.0f;
    for (int i = tid; i < n_rows; i += 1024) s += g_partials[i];
    float h = 0.0f;
    for (int k = tid; k < KC; k += 1024) {
        float p = (float)g_counts[k] / (float)n_rows;
        h -= p * logf(p + 1e-10f);
    }
    __shared__ float rs[1024];
    __shared__ float rh[1024];
    rs[tid] = s; rh[tid] = h;
    __syncthreads();
    for (int st = 512; st > 0; st >>= 1) {
        if (tid < st) { rs[tid] += rs[tid + st]; rh[tid] += rh[tid + st]; }
        __syncthreads();
    }
    if (tid == 0 && write_loss) {
        float mse = rs[0] / ((float)n_rows * (float)DD);
        float perplexity = expf(rh[0]);
        out[(size_t)n_rows * DD] = (1.0f + BETA_F) * mse - 0.01f * perplexity;
    }
}

// ============================================================================
extern "C" void kernel_launch(void* const* d_in, const int* in_sizes, int n_in,
                              void* d_out, int out_size) {
    (void)n_in;
    const float* Z = (const float*)d_in[0];   // z_e  [8,4096,256] fp32
    const float* W = (const float*)d_in[1];   // embed [2048,256] fp32
    float* out = (float*)d_out;

    int D = in_sizes[1] / KC;                  // 256
    int n_rows = in_sizes[0] / D;              // 32768
    long long nzq = (long long)n_rows * D;
    int write_loss = (out_size >= nzq + 1) ? 1 : 0;
    int write_idx  = (out_size >= nzq + 1 + n_rows) ? 1 : 0;

    cudaFuncSetAttribute(vq_hmma_kernel,
                         cudaFuncAttributeMaxDynamicSharedMemorySize, SMEM_TOTAL);

    vq_prep_e2_kernel<<<KC, 256>>>(W);                           // idx 0
    vq_prep_wbf_kernel<<<(KC * DD) / 256, 256>>>(W);             // idx 1
    vq_zero_ncand_kernel<<<(n_rows + 255) / 256, 256>>>(n_rows); // idx 2
    vq_hmma_kernel<<<n_rows / TILE_M, NTHREADS, SMEM_TOTAL>>>(Z); // idx 3 (profiled)
    vq_refine_gather_kernel<<<n_rows / 8, 256>>>(Z, W, out, n_rows, write_idx);
    vq_loss_kernel<<<1, 1024>>>(out, n_rows, write_loss);
}